// round 7
// baseline (speedup 1.0000x reference)
#include <cuda_runtime.h>
#include <cuda_bf16.h>
#include <cuda_fp16.h>
#include <cstdint>

// ============================================================================
// Problem constants
// ============================================================================
static constexpr int B_ROWS = 131072;
static constexpr int KC     = 512;
static constexpr int TM     = 128;
static constexpr int NTILES = B_ROWS / TM;   // 1024
static constexpr int NCTAS  = 148;           // persistent grid

// ============================================================================
// SMEM layout (bytes)  — all tile regions 1024-aligned for SW128
// ============================================================================
static constexpr int OFF_ZSQ  = 0;        // 128 f32
static constexpr int OFF_CSQ  = 512;      // 512 f32
static constexpr int OFF_MS   = 2560;     // M_s[128] + invs_s[128] = 1 KB
static constexpr int OFF_MST  = 3584;     // 4 grp x 128 rows x 4 f32 = 8 KB
static constexpr int OFF_RED  = 11776;    // warp partials + flag + dbl scratch
static constexpr int OFF_ZRAW = 12288;    // raw z tile fp32, 32 KB
static constexpr int OFF_AHI  = 45056;    // z-hi  128 x 128B = 16 KB
static constexpr int OFF_ALO  = 61440;    // 16 KB
static constexpr int OFF_BHI  = 77824;    // c-hi  512 x 128B = 64 KB
static constexpr int OFF_BLO  = 143360;   // 64 KB
static constexpr int SMEM_BYTES = 208896; // ~204 KB

__device__ float g_loss_partial[NCTAS];
__device__ unsigned int g_done;   // zero-init; reset by last CTA each run

#define SWZ(o) ((o) ^ (((o) >> 3) & 0x70))

// ============================================================================
// Helpers
// ============================================================================
__device__ __forceinline__ uint32_t smem_u32(const void* p) {
    uint32_t a;
    asm("{ .reg .u64 t; cvta.to.shared.u64 t, %1; cvt.u32.u64 %0, t; }" : "=r"(a) : "l"(p));
    return a;
}

__device__ __forceinline__ void ldsm4(uint32_t r[4], uint32_t addr) {
    asm volatile("ldmatrix.sync.aligned.m8n8.x4.shared.b16 {%0,%1,%2,%3}, [%4];"
                 : "=r"(r[0]), "=r"(r[1]), "=r"(r[2]), "=r"(r[3]) : "r"(addr));
}

__device__ __forceinline__ void mma16816(float* d, const uint32_t* a, uint32_t b0, uint32_t b1) {
    asm volatile("mma.sync.aligned.m16n8k16.row.col.f32.bf16.bf16.f32 "
                 "{%0,%1,%2,%3}, {%4,%5,%6,%7}, {%8,%9}, {%0,%1,%2,%3};"
                 : "+f"(d[0]), "+f"(d[1]), "+f"(d[2]), "+f"(d[3])
                 : "r"(a[0]), "r"(a[1]), "r"(a[2]), "r"(a[3]), "r"(b0), "r"(b1));
}

__device__ __forceinline__ void split2(float x, float y, uint32_t& hi, uint32_t& lo) {
    __nv_bfloat16 hx = __float2bfloat16(x), hy = __float2bfloat16(y);
    float rx = x - __bfloat162float(hx);
    float ry = y - __bfloat162float(hy);
    __nv_bfloat162 h(hx, hy);
    __nv_bfloat162 l(__float2bfloat16(rx), __float2bfloat16(ry));
    hi = *reinterpret_cast<uint32_t*>(&h);
    lo = *reinterpret_cast<uint32_t*>(&l);
}

__device__ __forceinline__ void cp_async16(uint32_t dst, const void* src) {
    asm volatile("cp.async.cg.shared.global [%0], [%1], 16;" :: "r"(dst), "l"(src));
}

// One 64-col chunk of cross2 for a 32-row warp tile (3 split terms fused).
// acc[64]: [tile(2)][nt(8)][4].
__device__ __forceinline__ void compute_chunk(
    float acc[64], uint32_t sb, uint32_t chbase,
    uint32_t aoff0, uint32_t aoff1, uint32_t bRowL, uint32_t bK16)
{
    #pragma unroll
    for (int i = 0; i < 64; i++) acc[i] = 0.f;
    #pragma unroll
    for (int ks = 0; ks < 4; ks++) {
        uint32_t a0[4], a1[4], l0[4], l1[4];
        ldsm4(a0, sb + OFF_AHI + SWZ(aoff0 + ks * 32));
        ldsm4(a1, sb + OFF_AHI + SWZ(aoff1 + ks * 32));
        ldsm4(l0, sb + OFF_ALO + SWZ(aoff0 + ks * 32));
        ldsm4(l1, sb + OFF_ALO + SWZ(aoff1 + ks * 32));
        #pragma unroll
        for (int p = 0; p < 4; p++) {
            const uint32_t bo = (chbase + p * 16 + bRowL) * 128 + bK16 + ks * 32;
            uint32_t bh[4], bl[4];
            ldsm4(bh, sb + OFF_BHI + SWZ(bo));
            ldsm4(bl, sb + OFF_BLO + SWZ(bo));
            float* A0 = acc + (p * 2) * 4;
            float* A1 = acc + (p * 2 + 1) * 4;
            float* B0 = acc + 32 + (p * 2) * 4;
            float* B1 = acc + 32 + (p * 2 + 1) * 4;
            mma16816(A0, a0, bh[0], bh[1]); mma16816(A1, a0, bh[2], bh[3]);
            mma16816(A0, a0, bl[0], bl[1]); mma16816(A1, a0, bl[2], bl[3]);
            mma16816(A0, l0, bh[0], bh[1]); mma16816(A1, l0, bh[2], bh[3]);
            mma16816(B0, a1, bh[0], bh[1]); mma16816(B1, a1, bh[2], bh[3]);
            mma16816(B0, a1, bl[0], bl[1]); mma16816(B1, a1, bl[2], bl[3]);
            mma16816(B0, l1, bh[0], bh[1]); mma16816(B1, l1, bh[2], bh[3]);
        }
    }
}

// ============================================================================
// Persistent kernel: 148 CTAs x 512 threads; warp = 32 rows x 128 cols
// ============================================================================
__global__ void __launch_bounds__(512, 1)
soft_kmeans_kernel(const float* __restrict__ z, const float* __restrict__ cc,
                   float* __restrict__ q_out, float* __restrict__ loss_out) {
    extern __shared__ char smem[];
    const uint32_t sb = smem_u32(smem);
    const int tid  = threadIdx.x;
    const int lane = tid & 31;
    const int wid  = tid >> 5;
    const int bid  = blockIdx.x;
    const int mt   = wid & 3;     // m32 tile: rows mt*32 .. mt*32+31
    const int grp  = wid >> 2;    // col group: cols grp*128 .. grp*128+127

    float* zsq_s  = reinterpret_cast<float*>(smem + OFF_ZSQ);
    float* csq_s  = reinterpret_cast<float*>(smem + OFF_CSQ);
    float* M_s    = reinterpret_cast<float*>(smem + OFF_MS);
    float* invs_s = M_s + 128;
    float* mst_s  = reinterpret_cast<float*>(smem + OFF_MST);
    float* red_s  = reinterpret_cast<float*>(smem + OFF_RED);
    unsigned int* flag_s = reinterpret_cast<unsigned int*>(smem + OFF_RED + 64);

    const float4* z4 = reinterpret_cast<const float4*>(z);

    // ---- prefetch first z tile --------------------------------------------
    {
        #pragma unroll
        for (int it = 0; it < 4; it++) {
            const int idx = it * 512 + tid;
            cp_async16(sb + OFF_ZRAW + (uint32_t)idx * 16,
                       z4 + (size_t)bid * 2048 + idx);
        }
        asm volatile("cp.async.commit_group;" ::: "memory");
    }

    // ---- load all 512 centers ONCE (split hi/lo + csq) ---------------------
    {
        const float4* ct = reinterpret_cast<const float4*>(cc);
        #pragma unroll 4
        for (int it = 0; it < 16; it++) {
            const int idx = it * 512 + tid;
            const int row = idx >> 4, c4 = idx & 15;
            const float4 v = ct[idx];
            float sq = v.x * v.x + v.y * v.y + v.z * v.z + v.w * v.w;
            sq += __shfl_xor_sync(~0u, sq, 1);
            sq += __shfl_xor_sync(~0u, sq, 2);
            sq += __shfl_xor_sync(~0u, sq, 4);
            sq += __shfl_xor_sync(~0u, sq, 8);
            if ((lane & 15) == 0) csq_s[row] = sq;
            uint2 hi, lo;
            split2(v.x, v.y, hi.x, lo.x);
            split2(v.z, v.w, hi.y, lo.y);
            const uint32_t so = SWZ((uint32_t)(row * 128 + c4 * 8));
            *reinterpret_cast<uint2*>(smem + OFF_BHI + so) = hi;
            *reinterpret_cast<uint2*>(smem + OFF_BLO + so) = lo;
        }
    }

    // ---- lane decodes ------------------------------------------------------
    const int l8 = lane & 7;
    const uint32_t aCol16 = ((lane >> 4) & 1) * 16;
    const uint32_t aRow0  = (uint32_t)(mt * 32 + ((lane >> 3) & 1) * 8 + l8);
    const uint32_t aoff0  = aRow0 * 128 + aCol16;
    const uint32_t aoff1  = (aRow0 + 16) * 128 + aCol16;
    const uint32_t bRowL  = ((lane >> 4) & 1) * 8 + l8;
    const uint32_t bK16   = ((lane >> 3) & 1) * 16;

    const int rq = lane >> 2;
    int row_j[4];
    row_j[0] = mt * 32 + rq;       row_j[1] = row_j[0] + 8;
    row_j[2] = row_j[0] + 16;      row_j[3] = row_j[0] + 24;

    float cta_loss = 0.f;

    // ======================= tile loop =====================================
    for (int tile = bid; tile < NTILES; tile += NCTAS) {
        asm volatile("cp.async.wait_group 0;" ::: "memory");
        __syncthreads();   // prev pass B done (A free) + raw tile present

        // ---- split z tile from ZRAW into A hi/lo (pre-scaled x2) ----------
        #pragma unroll
        for (int it = 0; it < 4; it++) {
            const int idx = it * 512 + tid;
            const int row = idx >> 4, c4 = idx & 15;
            const float4 v = *reinterpret_cast<const float4*>(smem + OFF_ZRAW + idx * 16);
            float sq = v.x * v.x + v.y * v.y + v.z * v.z + v.w * v.w;
            sq += __shfl_xor_sync(~0u, sq, 1);
            sq += __shfl_xor_sync(~0u, sq, 2);
            sq += __shfl_xor_sync(~0u, sq, 4);
            sq += __shfl_xor_sync(~0u, sq, 8);
            if ((lane & 15) == 0) zsq_s[row] = sq;
            uint2 hi, lo;
            split2(2.f * v.x, 2.f * v.y, hi.x, lo.x);
            split2(2.f * v.z, 2.f * v.w, hi.y, lo.y);
            const uint32_t so = SWZ((uint32_t)(row * 128 + c4 * 8));
            *reinterpret_cast<uint2*>(smem + OFF_AHI + so) = hi;
            *reinterpret_cast<uint2*>(smem + OFF_ALO + so) = lo;
        }
        __syncthreads();   // A, zsq (and B on first iter) visible

        // ---- kick prefetch of next tile -----------------------------------
        const int ntile = tile + NCTAS;
        if (ntile < NTILES) {
            #pragma unroll
            for (int it = 0; it < 4; it++) {
                const int idx = it * 512 + tid;
                cp_async16(sb + OFF_ZRAW + (uint32_t)idx * 16,
                           z4 + (size_t)ntile * 2048 + idx);
            }
        }
        asm volatile("cp.async.commit_group;" ::: "memory");

        float zq[4];
        #pragma unroll
        for (int j = 0; j < 4; j++) zq[j] = zsq_s[row_j[j]];

        // ---- PASS A: online (m, s, t) over this warp's 128 cols -----------
        float m[4], s[4], tl[4];
        #pragma unroll
        for (int j = 0; j < 4; j++) { m[j] = -1e30f; s[j] = 0.f; tl[j] = 0.f; }

        #pragma unroll
        for (int ci = 0; ci < 2; ci++) {
            const uint32_t chbase = (uint32_t)(grp * 128 + ci * 64);
            float acc[64];
            compute_chunk(acc, sb, chbase, aoff0, aoff1, bRowL, bK16);

            float cm[4] = {-1e30f, -1e30f, -1e30f, -1e30f};
            #pragma unroll
            for (int nt = 0; nt < 8; nt++) {
                const float2 cs = *reinterpret_cast<const float2*>(
                    csq_s + chbase + nt * 8 + (lane & 3) * 2);
                float* A = acc + nt * 4;
                float* B = acc + 32 + nt * 4;
                A[0] -= zq[0] + cs.x;  A[1] -= zq[0] + cs.y;
                A[2] -= zq[1] + cs.x;  A[3] -= zq[1] + cs.y;
                B[0] -= zq[2] + cs.x;  B[1] -= zq[2] + cs.y;
                B[2] -= zq[3] + cs.x;  B[3] -= zq[3] + cs.y;
                cm[0] = fmaxf(cm[0], fmaxf(A[0], A[1]));
                cm[1] = fmaxf(cm[1], fmaxf(A[2], A[3]));
                cm[2] = fmaxf(cm[2], fmaxf(B[0], B[1]));
                cm[3] = fmaxf(cm[3], fmaxf(B[2], B[3]));
            }
            #pragma unroll
            for (int j = 0; j < 4; j++) {
                cm[j] = fmaxf(cm[j], __shfl_xor_sync(~0u, cm[j], 1));
                cm[j] = fmaxf(cm[j], __shfl_xor_sync(~0u, cm[j], 2));
                const float nm = fmaxf(m[j], cm[j]);
                const float f = __expf(m[j] - nm);
                s[j] *= f; tl[j] *= f; m[j] = nm;
            }
            #pragma unroll
            for (int nt = 0; nt < 8; nt++) {
                float* A = acc + nt * 4;
                float* B = acc + 32 + nt * 4;
                float e;
                e = __expf(A[0] - m[0]); s[0] += e; tl[0] -= e * A[0];
                e = __expf(A[1] - m[0]); s[0] += e; tl[0] -= e * A[1];
                e = __expf(A[2] - m[1]); s[1] += e; tl[1] -= e * A[2];
                e = __expf(A[3] - m[1]); s[1] += e; tl[1] -= e * A[3];
                e = __expf(B[0] - m[2]); s[2] += e; tl[2] -= e * B[0];
                e = __expf(B[1] - m[2]); s[2] += e; tl[2] -= e * B[1];
                e = __expf(B[2] - m[3]); s[3] += e; tl[3] -= e * B[2];
                e = __expf(B[3] - m[3]); s[3] += e; tl[3] -= e * B[3];
            }
        }

        // quad reduce + publish (m, s, t)
        #pragma unroll
        for (int j = 0; j < 4; j++) {
            s[j]  += __shfl_xor_sync(~0u, s[j], 1);
            s[j]  += __shfl_xor_sync(~0u, s[j], 2);
            tl[j] += __shfl_xor_sync(~0u, tl[j], 1);
            tl[j] += __shfl_xor_sync(~0u, tl[j], 2);
        }
        if ((lane & 3) == 0) {
            #pragma unroll
            for (int j = 0; j < 4; j++) {
                float* p = mst_s + (size_t)(grp * 128 + row_j[j]) * 4;
                p[0] = m[j]; p[1] = s[j]; p[2] = tl[j];
            }
        }
        __syncthreads();

        // ---- merge 4 groups per row (thread = row) ------------------------
        float lossr = 0.f;
        if (tid < TM) {
            float Mv = -1e30f;
            float mg[4], sg[4], tg[4];
            #pragma unroll
            for (int g = 0; g < 4; g++) {
                const float* p = mst_s + (size_t)(g * 128 + tid) * 4;
                mg[g] = p[0]; sg[g] = p[1]; tg[g] = p[2];
                Mv = fmaxf(Mv, mg[g]);
            }
            float sF = 0.f, tF = 0.f;
            #pragma unroll
            for (int g = 0; g < 4; g++) {
                const float f = __expf(mg[g] - Mv);
                sF += sg[g] * f; tF += tg[g] * f;
            }
            const float inv = 1.f / sF;
            M_s[tid] = Mv; invs_s[tid] = inv;
            lossr = tF * inv;
        }
        #pragma unroll
        for (int o = 16; o; o >>= 1) lossr += __shfl_xor_sync(~0u, lossr, o);
        if (wid < 4 && lane == 0) red_s[wid] = lossr;
        __syncthreads();
        if (tid == 0) cta_loss += red_s[0] + red_s[1] + red_s[2] + red_s[3];

        // ---- PASS B: recompute + direct q store ---------------------------
        float Mj[4], ij[4];
        #pragma unroll
        for (int j = 0; j < 4; j++) { Mj[j] = M_s[row_j[j]]; ij[j] = invs_s[row_j[j]]; }
        float* qt = q_out + (size_t)tile * TM * KC;

        #pragma unroll
        for (int ci = 0; ci < 2; ci++) {
            const uint32_t chbase = (uint32_t)(grp * 128 + ci * 64);
            float acc[64];
            compute_chunk(acc, sb, chbase, aoff0, aoff1, bRowL, bK16);

            #pragma unroll
            for (int nt = 0; nt < 8; nt++) {
                const int col = (int)chbase + nt * 8 + (lane & 3) * 2;
                const float2 cs = *reinterpret_cast<const float2*>(csq_s + col);
                float* A = acc + nt * 4;
                float* B = acc + 32 + nt * 4;
                float2 o;
                o.x = __expf(A[0] - zq[0] - cs.x - Mj[0]) * ij[0];
                o.y = __expf(A[1] - zq[0] - cs.y - Mj[0]) * ij[0];
                *reinterpret_cast<float2*>(qt + (size_t)row_j[0] * KC + col) = o;
                o.x = __expf(A[2] - zq[1] - cs.x - Mj[1]) * ij[1];
                o.y = __expf(A[3] - zq[1] - cs.y - Mj[1]) * ij[1];
                *reinterpret_cast<float2*>(qt + (size_t)row_j[1] * KC + col) = o;
                o.x = __expf(B[0] - zq[2] - cs.x - Mj[2]) * ij[2];
                o.y = __expf(B[1] - zq[2] - cs.y - Mj[2]) * ij[2];
                *reinterpret_cast<float2*>(qt + (size_t)row_j[2] * KC + col) = o;
                o.x = __expf(B[2] - zq[3] - cs.x - Mj[3]) * ij[3];
                o.y = __expf(B[3] - zq[3] - cs.y - Mj[3]) * ij[3];
                *reinterpret_cast<float2*>(qt + (size_t)row_j[3] * KC + col) = o;
            }
        }
    } // tile loop

    if (tid == 0) g_loss_partial[bid] = cta_loss;

    // ---- last-CTA loss finalize (deterministic fixed-order sum) ------------
    __threadfence();
    if (tid == 0) {
        const unsigned int old = atomicAdd(&g_done, 1u);
        *flag_s = (old == (unsigned int)(NCTAS - 1)) ? 1u : 0u;
    }
    __syncthreads();
    if (*flag_s) {
        double a = (tid < NCTAS) ? (double)g_loss_partial[tid] : 0.0;
        #pragma unroll
        for (int o = 16; o; o >>= 1) a += __shfl_xor_sync(~0u, a, o);
        double* dred = reinterpret_cast<double*>(smem + OFF_RED + 128);
        if (lane == 0) dred[wid] = a;
        __syncthreads();
        if (tid == 0) {
            double t = 0.0;
            #pragma unroll
            for (int i = 0; i < 16; i++) t += dred[i];
            if (loss_out) *loss_out = (float)(t / (double)B_ROWS);
            g_done = 0;   // reset for next graph replay
        }
    }
}

// ============================================================================
// Launch
// ============================================================================
extern "C" void kernel_launch(void* const* d_in, const int* in_sizes, int n_in,
                              void* d_out, int out_size) {
    const float* z  = (const float*)d_in[0];
    const float* cc = (const float*)d_in[1];
    float* q = (float*)d_out;

    const long long q_elems = (long long)B_ROWS * KC;  // 67108864
    float* loss_out = ((long long)out_size > q_elems) ? (q + q_elems) : nullptr;

    cudaFuncSetAttribute(soft_kmeans_kernel,
                         cudaFuncAttributeMaxDynamicSharedMemorySize, SMEM_BYTES);
    soft_kmeans_kernel<<<NCTAS, 512, SMEM_BYTES>>>(z, cc, q, loss_out);
}

// round 8
// speedup vs baseline: 1.2283x; 1.2283x over previous
#include <cuda_runtime.h>
#include <cuda_bf16.h>
#include <cuda_fp16.h>
#include <cstdint>

// ============================================================================
// Problem constants
// ============================================================================
static constexpr int B_ROWS = 131072;
static constexpr int KC     = 512;
static constexpr int TM     = 128;
static constexpr int NTILES = B_ROWS / TM;   // 1024

// ============================================================================
// SMEM layout (bytes)
// ============================================================================
static constexpr int OFF_ZSQ = 0;        // 128 f32
static constexpr int OFF_CSQ = 512;      // 512 f32
static constexpr int OFF_W   = 2560;     // 128*9 f32 = 4608 B (chunk-max snapshots -> weights)
static constexpr int OFF_MST = 7168;     // 4 grp x 128 rows x 4 f32 = 8192 B
static constexpr int OFF_RED = 15360;    // warp partials + flag + dbl scratch (1 KB)
static constexpr int OFF_AHI = 16384;    // z-hi  128 x 128B = 16 KB
static constexpr int OFF_ALO = 32768;    // 16 KB
static constexpr int OFF_BHI = 49152;    // c-hi  512 x 128B = 64 KB
static constexpr int OFF_BLO = 114688;   // 64 KB
static constexpr int SMEM_BYTES = 180224;
// e-staging for chunk n aliases B cluster-rows [64n,64n+64): tile rows 0-63 go
// into BHI + n*8192, rows 64-127 into BLO + n*8192 (dead after chunk-n MMA,
// and chunk n is only ever read by column-group n>>1).

__device__ float g_loss_partial[NTILES];
__device__ unsigned int g_done;   // zero-init; reset by last CTA each run

#define SWZ(o) ((o) ^ (((o) >> 3) & 0x70))

// ============================================================================
// Helpers
// ============================================================================
__device__ __forceinline__ uint32_t smem_u32(const void* p) {
    uint32_t a;
    asm("{ .reg .u64 t; cvta.to.shared.u64 t, %1; cvt.u32.u64 %0, t; }" : "=r"(a) : "l"(p));
    return a;
}

__device__ __forceinline__ void ldsm4(uint32_t r[4], uint32_t addr) {
    asm volatile("ldmatrix.sync.aligned.m8n8.x4.shared.b16 {%0,%1,%2,%3}, [%4];"
                 : "=r"(r[0]), "=r"(r[1]), "=r"(r[2]), "=r"(r[3]) : "r"(addr));
}

__device__ __forceinline__ void mma16816(float* d, const uint32_t* a, uint32_t b0, uint32_t b1) {
    asm volatile("mma.sync.aligned.m16n8k16.row.col.f32.bf16.bf16.f32 "
                 "{%0,%1,%2,%3}, {%4,%5,%6,%7}, {%8,%9}, {%0,%1,%2,%3};"
                 : "+f"(d[0]), "+f"(d[1]), "+f"(d[2]), "+f"(d[3])
                 : "r"(a[0]), "r"(a[1]), "r"(a[2]), "r"(a[3]), "r"(b0), "r"(b1));
}

__device__ __forceinline__ void split2(float x, float y, uint32_t& hi, uint32_t& lo) {
    __nv_bfloat16 hx = __float2bfloat16(x), hy = __float2bfloat16(y);
    float rx = x - __bfloat162float(hx);
    float ry = y - __bfloat162float(hy);
    __nv_bfloat162 h(hx, hy);
    __nv_bfloat162 l(__float2bfloat16(rx), __float2bfloat16(ry));
    hi = *reinterpret_cast<uint32_t*>(&h);
    lo = *reinterpret_cast<uint32_t*>(&l);
}

// One 64-col chunk of cross2 for a 32-row warp tile (3 split terms fused).
// acc[64]: [rowpair(2)][nt(8)][4]; A fragments loaded inside (caps regs).
__device__ __forceinline__ void compute_chunk(
    float acc[64], uint32_t sb, uint32_t chbase,
    uint32_t aoff0, uint32_t aoff1, uint32_t bRowL, uint32_t bK16)
{
    #pragma unroll
    for (int i = 0; i < 64; i++) acc[i] = 0.f;
    #pragma unroll
    for (int ks = 0; ks < 4; ks++) {
        uint32_t a0[4], a1[4], l0[4], l1[4];
        ldsm4(a0, sb + OFF_AHI + SWZ(aoff0 + ks * 32));
        ldsm4(a1, sb + OFF_AHI + SWZ(aoff1 + ks * 32));
        ldsm4(l0, sb + OFF_ALO + SWZ(aoff0 + ks * 32));
        ldsm4(l1, sb + OFF_ALO + SWZ(aoff1 + ks * 32));
        #pragma unroll
        for (int p = 0; p < 4; p++) {
            const uint32_t bo = (chbase + p * 16 + bRowL) * 128 + bK16 + ks * 32;
            uint32_t bh[4], bl[4];
            ldsm4(bh, sb + OFF_BHI + SWZ(bo));
            ldsm4(bl, sb + OFF_BLO + SWZ(bo));
            float* A0 = acc + (p * 2) * 4;
            float* A1 = acc + (p * 2 + 1) * 4;
            float* B0 = acc + 32 + (p * 2) * 4;
            float* B1 = acc + 32 + (p * 2 + 1) * 4;
            mma16816(A0, a0, bh[0], bh[1]); mma16816(A1, a0, bh[2], bh[3]);
            mma16816(A0, a0, bl[0], bl[1]); mma16816(A1, a0, bl[2], bl[3]);
            mma16816(A0, l0, bh[0], bh[1]); mma16816(A1, l0, bh[2], bh[3]);
            mma16816(B0, a1, bh[0], bh[1]); mma16816(B1, a1, bh[2], bh[3]);
            mma16816(B0, a1, bl[0], bl[1]); mma16816(B1, a1, bl[2], bl[3]);
            mma16816(B0, l1, bh[0], bh[1]); mma16816(B1, l1, bh[2], bh[3]);
        }
    }
}

// ============================================================================
// Main kernel: one CTA per 128-row tile, 512 threads
// 16 warps = 4 m32-tiles x 4 col-groups (group g owns chunks 2g, 2g+1)
// ============================================================================
__global__ void __launch_bounds__(512, 1)
soft_kmeans_kernel(const float* __restrict__ z, const float* __restrict__ cc,
                   float* __restrict__ q_out, float* __restrict__ loss_out) {
    extern __shared__ char smem[];
    const uint32_t sb = smem_u32(smem);
    const int tid  = threadIdx.x;
    const int lane = tid & 31;
    const int wid  = tid >> 5;
    const int tile = blockIdx.x;
    const int mt   = wid & 3;     // rows mt*32 .. mt*32+31
    const int grp  = wid >> 2;    // cols grp*128 .. grp*128+127

    float* zsq_s = reinterpret_cast<float*>(smem + OFF_ZSQ);
    float* csq_s = reinterpret_cast<float*>(smem + OFF_CSQ);
    float* w_s   = reinterpret_cast<float*>(smem + OFF_W);
    float* mst_s = reinterpret_cast<float*>(smem + OFF_MST);
    float* red_s = reinterpret_cast<float*>(smem + OFF_RED);
    unsigned int* flag_s = reinterpret_cast<unsigned int*>(smem + OFF_RED + 64);

    // ---- Phase 0a: z tile, coalesced float4; split hi/lo (pre-scaled x2) ---
    {
        const float4* zt = reinterpret_cast<const float4*>(z) + (size_t)tile * (TM * 64 / 4);
        #pragma unroll
        for (int it = 0; it < 4; it++) {
            const int idx = it * 512 + tid;
            const int row = idx >> 4, c4 = idx & 15;
            const float4 v = zt[idx];
            float sq = v.x * v.x + v.y * v.y + v.z * v.z + v.w * v.w;
            sq += __shfl_xor_sync(~0u, sq, 1);
            sq += __shfl_xor_sync(~0u, sq, 2);
            sq += __shfl_xor_sync(~0u, sq, 4);
            sq += __shfl_xor_sync(~0u, sq, 8);
            if ((lane & 15) == 0) zsq_s[row] = sq;
            uint2 hi, lo;
            split2(2.f * v.x, 2.f * v.y, hi.x, lo.x);
            split2(2.f * v.z, 2.f * v.w, hi.y, lo.y);
            const uint32_t so = SWZ((uint32_t)(row * 128 + c4 * 8));
            *reinterpret_cast<uint2*>(smem + OFF_AHI + so) = hi;
            *reinterpret_cast<uint2*>(smem + OFF_ALO + so) = lo;
        }
    }
    // ---- Phase 0b: all 512 centers ----------------------------------------
    {
        const float4* ct = reinterpret_cast<const float4*>(cc);
        #pragma unroll 4
        for (int it = 0; it < 16; it++) {
            const int idx = it * 512 + tid;
            const int row = idx >> 4, c4 = idx & 15;
            const float4 v = ct[idx];
            float sq = v.x * v.x + v.y * v.y + v.z * v.z + v.w * v.w;
            sq += __shfl_xor_sync(~0u, sq, 1);
            sq += __shfl_xor_sync(~0u, sq, 2);
            sq += __shfl_xor_sync(~0u, sq, 4);
            sq += __shfl_xor_sync(~0u, sq, 8);
            if ((lane & 15) == 0) csq_s[row] = sq;
            uint2 hi, lo;
            split2(v.x, v.y, hi.x, lo.x);
            split2(v.z, v.w, hi.y, lo.y);
            const uint32_t so = SWZ((uint32_t)(row * 128 + c4 * 8));
            *reinterpret_cast<uint2*>(smem + OFF_BHI + so) = hi;
            *reinterpret_cast<uint2*>(smem + OFF_BLO + so) = lo;
        }
    }
    __syncthreads();

    // ---- lane decodes ------------------------------------------------------
    const int l8 = lane & 7;
    const uint32_t aCol16 = ((lane >> 4) & 1) * 16;
    const uint32_t aRow0  = (uint32_t)(mt * 32 + ((lane >> 3) & 1) * 8 + l8);
    const uint32_t aoff0  = aRow0 * 128 + aCol16;
    const uint32_t aoff1  = (aRow0 + 16) * 128 + aCol16;
    const uint32_t bRowL  = ((lane >> 4) & 1) * 8 + l8;
    const uint32_t bK16   = ((lane >> 3) & 1) * 16;

    const int rq = lane >> 2;
    int row_j[4];
    row_j[0] = mt * 32 + rq;   row_j[1] = row_j[0] + 8;
    row_j[2] = row_j[0] + 16;  row_j[3] = row_j[0] + 24;

    float zq[4];
    #pragma unroll
    for (int j = 0; j < 4; j++) zq[j] = zsq_s[row_j[j]];

    // e-staging bases (all 4 rows of a warp live in the same B half)
    uint32_t ebase[4];
    #pragma unroll
    for (int j = 0; j < 4; j++) {
        const int r = row_j[j];
        ebase[j] = (r < 64 ? OFF_BHI + (uint32_t)r * 128
                           : OFF_BLO + (uint32_t)(r - 64) * 128) + (lane & 3) * 4;
    }

    float m[4], s[4], tl[4];
    #pragma unroll
    for (int j = 0; j < 4; j++) { m[j] = -1e30f; s[j] = 0.f; tl[j] = 0.f; }

    // ---- Pass 1: group g processes its 2 chunks, decoupled from others -----
    #pragma unroll
    for (int ci = 0; ci < 2; ci++) {
        const int ch = grp * 2 + ci;
        const uint32_t chbase = (uint32_t)ch * 64;

        float acc[64];
        compute_chunk(acc, sb, chbase, aoff0, aoff1, bRowL, bK16);

        // y = cross2 - zsq - csq = -dist; chunk max per row-quad
        float cm[4] = {-1e30f, -1e30f, -1e30f, -1e30f};
        #pragma unroll
        for (int nt = 0; nt < 8; nt++) {
            const float2 cs = *reinterpret_cast<const float2*>(
                csq_s + chbase + nt * 8 + (lane & 3) * 2);
            float* A = acc + nt * 4;
            float* B = acc + 32 + nt * 4;
            A[0] -= zq[0] + cs.x;  A[1] -= zq[0] + cs.y;
            A[2] -= zq[1] + cs.x;  A[3] -= zq[1] + cs.y;
            B[0] -= zq[2] + cs.x;  B[1] -= zq[2] + cs.y;
            B[2] -= zq[3] + cs.x;  B[3] -= zq[3] + cs.y;
            cm[0] = fmaxf(cm[0], fmaxf(A[0], A[1]));
            cm[1] = fmaxf(cm[1], fmaxf(A[2], A[3]));
            cm[2] = fmaxf(cm[2], fmaxf(B[0], B[1]));
            cm[3] = fmaxf(cm[3], fmaxf(B[2], B[3]));
        }
        #pragma unroll
        for (int j = 0; j < 4; j++) {
            cm[j] = fmaxf(cm[j], __shfl_xor_sync(~0u, cm[j], 1));
            cm[j] = fmaxf(cm[j], __shfl_xor_sync(~0u, cm[j], 2));
            const float nm = fmaxf(m[j], cm[j]);
            const float f = __expf(m[j] - nm);
            s[j] *= f; tl[j] *= f; m[j] = nm;
        }

        // exps + running sums into regs BEFORE the group barrier
        uint32_t hp[4][8];
        #pragma unroll
        for (int nt = 0; nt < 8; nt++) {
            float* A = acc + nt * 4;
            float* B = acc + 32 + nt * 4;
            const float e00 = __expf(A[0] - m[0]), e01 = __expf(A[1] - m[0]);
            const float e10 = __expf(A[2] - m[1]), e11 = __expf(A[3] - m[1]);
            const float e20 = __expf(B[0] - m[2]), e21 = __expf(B[1] - m[2]);
            const float e30 = __expf(B[2] - m[3]), e31 = __expf(B[3] - m[3]);
            s[0] += e00 + e01;  tl[0] -= e00 * A[0] + e01 * A[1];
            s[1] += e10 + e11;  tl[1] -= e10 * A[2] + e11 * A[3];
            s[2] += e20 + e21;  tl[2] -= e20 * B[0] + e21 * B[1];
            s[3] += e30 + e31;  tl[3] -= e30 * B[2] + e31 * B[3];
            const __half2 h0 = __floats2half2_rn(e00, e01);
            const __half2 h1 = __floats2half2_rn(e10, e11);
            const __half2 h2 = __floats2half2_rn(e20, e21);
            const __half2 h3 = __floats2half2_rn(e30, e31);
            hp[0][nt] = *reinterpret_cast<const uint32_t*>(&h0);
            hp[1][nt] = *reinterpret_cast<const uint32_t*>(&h1);
            hp[2][nt] = *reinterpret_cast<const uint32_t*>(&h2);
            hp[3][nt] = *reinterpret_cast<const uint32_t*>(&h3);
        }

        // group-local barrier: the 4 warps of group g are the ONLY readers of
        // B[ch]; once they arrive, aliasing B[ch] with e is safe.
        asm volatile("bar.sync %0, %1;" :: "r"(grp + 1), "r"(128) : "memory");

        const uint32_t chOff = (uint32_t)ch * 8192;
        #pragma unroll
        for (int j = 0; j < 4; j++) {
            const uint32_t eb = ebase[j] + chOff;
            #pragma unroll
            for (int nt = 0; nt < 8; nt++) {
                *reinterpret_cast<uint32_t*>(smem + eb + (uint32_t)((nt ^ rq) * 16)) = hp[j][nt];
            }
        }
        if ((lane & 3) == 0) {
            #pragma unroll
            for (int j = 0; j < 4; j++) w_s[row_j[j] * 9 + ch] = m[j];
        }
    }

    // ---- group-local row reductions + publish (m, s, t) --------------------
    #pragma unroll
    for (int j = 0; j < 4; j++) {
        s[j]  += __shfl_xor_sync(~0u, s[j], 1);
        s[j]  += __shfl_xor_sync(~0u, s[j], 2);
        tl[j] += __shfl_xor_sync(~0u, tl[j], 1);
        tl[j] += __shfl_xor_sync(~0u, tl[j], 2);
    }
    if ((lane & 3) == 0) {
        #pragma unroll
        for (int j = 0; j < 4; j++) {
            float* p = mst_s + (size_t)(grp * 128 + row_j[j]) * 4;
            p[0] = m[j]; p[1] = s[j]; p[2] = tl[j];
        }
    }
    __syncthreads();

    // ---- merge 4 groups per row (thread = row), weights, per-row loss ------
    float lossr = 0.f;
    if (tid < TM) {
        float Mv = -1e30f;
        float mg[4], sg[4], tg[4];
        #pragma unroll
        for (int g = 0; g < 4; g++) {
            const float* p = mst_s + (size_t)(g * 128 + tid) * 4;
            mg[g] = p[0]; sg[g] = p[1]; tg[g] = p[2];
            Mv = fmaxf(Mv, mg[g]);
        }
        float sF = 0.f, tF = 0.f;
        #pragma unroll
        for (int g = 0; g < 4; g++) {
            const float f = __expf(mg[g] - Mv);
            sF += sg[g] * f; tF += tg[g] * f;
        }
        const float inv = 1.f / sF;
        lossr = tF * inv;
        #pragma unroll
        for (int c = 0; c < 8; c++)
            w_s[tid * 9 + c] = __expf(w_s[tid * 9 + c] - Mv) * inv;
    }
    #pragma unroll
    for (int o = 16; o; o >>= 1) lossr += __shfl_xor_sync(~0u, lossr, o);
    if (wid < 4 && lane == 0) red_s[wid] = lossr;
    __syncthreads();   // w_s + red_s ready
    if (tid == 0)
        g_loss_partial[tile] = red_s[0] + red_s[1] + red_s[2] + red_s[3];

    // ---- Pass 2: coalesced q write (16 warps x 32 rows x 128 cols) ---------
    {
        const int rbase = (wid >> 2) * 32;
        const int cb = (wid & 3) * 128 + lane * 4;
        const int ch = cb >> 6;
        const uint32_t chOff = (uint32_t)ch * 8192;
        const uint32_t inrow = (uint32_t)(lane & 15) * 8;
        float* qb = q_out + (size_t)tile * TM * KC + cb;
        #pragma unroll 4
        for (int r = 0; r < 32; r++) {
            const int row = rbase + r;
            const uint32_t base = (row < 64 ? OFF_BHI + (uint32_t)row * 128
                                            : OFF_BLO + (uint32_t)(row - 64) * 128) + chOff;
            const uint2 u = *reinterpret_cast<const uint2*>(
                smem + base + (inrow ^ (uint32_t)((row & 7) * 16)));
            const float2 f01 = __half22float2(*reinterpret_cast<const __half2*>(&u.x));
            const float2 f23 = __half22float2(*reinterpret_cast<const __half2*>(&u.y));
            const float w = w_s[row * 9 + ch];
            float4 o;
            o.x = f01.x * w; o.y = f01.y * w; o.z = f23.x * w; o.w = f23.y * w;
            *reinterpret_cast<float4*>(qb + (size_t)row * KC) = o;
        }
    }

    // ---- last-CTA loss finalize (deterministic fixed-order sum) ------------
    __threadfence();
    if (tid == 0) {
        const unsigned int old = atomicAdd(&g_done, 1u);
        *flag_s = (old == (unsigned int)(NTILES - 1)) ? 1u : 0u;
    }
    __syncthreads();
    if (*flag_s) {
        double a = 0.0;
        for (int i = tid; i < NTILES; i += 512) a += (double)g_loss_partial[i];
        #pragma unroll
        for (int o = 16; o; o >>= 1) a += __shfl_xor_sync(~0u, a, o);
        double* dred = reinterpret_cast<double*>(smem + OFF_RED + 128);
        if (lane == 0) dred[wid] = a;
        __syncthreads();
        if (tid == 0) {
            double t = 0.0;
            #pragma unroll
            for (int i = 0; i < 16; i++) t += dred[i];
            if (loss_out) *loss_out = (float)(t / (double)B_ROWS);
            g_done = 0;   // reset for next graph replay
        }
    }
}

// ============================================================================
// Launch
// ============================================================================
extern "C" void kernel_launch(void* const* d_in, const int* in_sizes, int n_in,
                              void* d_out, int out_size) {
    const float* z  = (const float*)d_in[0];
    const float* cc = (const float*)d_in[1];
    float* q = (float*)d_out;

    const long long q_elems = (long long)B_ROWS * KC;  // 67108864
    float* loss_out = ((long long)out_size > q_elems) ? (q + q_elems) : nullptr;

    cudaFuncSetAttribute(soft_kmeans_kernel,
                         cudaFuncAttributeMaxDynamicSharedMemorySize, SMEM_BYTES);
    soft_kmeans_kernel<<<NTILES, 512, SMEM_BYTES>>>(z, cc, q, loss_out);
}

// round 9
// speedup vs baseline: 1.3262x; 1.0797x over previous
#include <cuda_runtime.h>
#include <cuda_bf16.h>
#include <cuda_fp16.h>
#include <cstdint>

// ============================================================================
// Problem constants
// ============================================================================
static constexpr int B_ROWS = 131072;
static constexpr int KC     = 512;
static constexpr int TM     = 128;
static constexpr int NTILES = B_ROWS / TM;   // 1024

static constexpr float LOG2E = 1.4426950408889634f;
static constexpr float LN2   = 0.6931471805599453f;

// ============================================================================
// SMEM layout (bytes)
// ============================================================================
static constexpr int OFF_ZSQ = 0;        // 128 f32 (log2e-scaled)
static constexpr int OFF_CSQ = 512;      // 512 f32 (NEGATED, log2e-scaled)
static constexpr int OFF_W   = 2560;     // 128*9 f32 (chunk-max snapshots -> weights)
static constexpr int OFF_MST = 7168;     // 4 grp x 128 rows x 4 f32
static constexpr int OFF_RED = 15360;    // warp partials + flag + dbl scratch
static constexpr int OFF_AHI = 16384;    // z-hi  128 x 128B = 16 KB
static constexpr int OFF_ALO = 32768;    // 16 KB
static constexpr int OFF_BHI = 49152;    // c-hi  512 x 128B = 64 KB
static constexpr int OFF_BLO = 114688;   // 64 KB
static constexpr int SMEM_BYTES = 180224;
// e-staging for chunk n aliases B cluster-rows [64n,64n+64): tile rows 0-63 go
// into BHI + n*8192, rows 64-127 into BLO + n*8192 (dead after chunk-n MMA,
// and chunk n is only ever read by column-group n>>1).

__device__ float g_loss_partial[NTILES];
__device__ unsigned int g_done;   // zero-init; reset by last CTA each run

#define SWZ(o) ((o) ^ (((o) >> 3) & 0x70))

// ============================================================================
// Helpers
// ============================================================================
__device__ __forceinline__ uint32_t smem_u32(const void* p) {
    uint32_t a;
    asm("{ .reg .u64 t; cvta.to.shared.u64 t, %1; cvt.u32.u64 %0, t; }" : "=r"(a) : "l"(p));
    return a;
}

__device__ __forceinline__ float ex2f(float x) {   // bare MUFU.EX2 (log2 domain)
    float r;
    asm("ex2.approx.ftz.f32 %0, %1;" : "=f"(r) : "f"(x));
    return r;
}

__device__ __forceinline__ void ldsm4(uint32_t r[4], uint32_t addr) {
    asm volatile("ldmatrix.sync.aligned.m8n8.x4.shared.b16 {%0,%1,%2,%3}, [%4];"
                 : "=r"(r[0]), "=r"(r[1]), "=r"(r[2]), "=r"(r[3]) : "r"(addr));
}

__device__ __forceinline__ void mma16816(float* d, const uint32_t* a, uint32_t b0, uint32_t b1) {
    asm volatile("mma.sync.aligned.m16n8k16.row.col.f32.bf16.bf16.f32 "
                 "{%0,%1,%2,%3}, {%4,%5,%6,%7}, {%8,%9}, {%0,%1,%2,%3};"
                 : "+f"(d[0]), "+f"(d[1]), "+f"(d[2]), "+f"(d[3])
                 : "r"(a[0]), "r"(a[1]), "r"(a[2]), "r"(a[3]), "r"(b0), "r"(b1));
}

__device__ __forceinline__ void split2(float x, float y, uint32_t& hi, uint32_t& lo) {
    __nv_bfloat16 hx = __float2bfloat16(x), hy = __float2bfloat16(y);
    float rx = x - __bfloat162float(hx);
    float ry = y - __bfloat162float(hy);
    __nv_bfloat162 h(hx, hy);
    __nv_bfloat162 l(__float2bfloat16(rx), __float2bfloat16(ry));
    hi = *reinterpret_cast<uint32_t*>(&h);
    lo = *reinterpret_cast<uint32_t*>(&l);
}

// One 64-col chunk of cross' for a 32-row warp tile (3 split terms fused).
// acc[64]: [rowpair(2)][nt(8)][4]; A fragments loaded inside (caps regs).
__device__ __forceinline__ void compute_chunk(
    float acc[64], uint32_t sb, uint32_t chbase,
    uint32_t aoff0, uint32_t aoff1, uint32_t bRowL, uint32_t bK16)
{
    #pragma unroll
    for (int i = 0; i < 64; i++) acc[i] = 0.f;
    #pragma unroll
    for (int ks = 0; ks < 4; ks++) {
        uint32_t a0[4], a1[4], l0[4], l1[4];
        ldsm4(a0, sb + OFF_AHI + SWZ(aoff0 + ks * 32));
        ldsm4(a1, sb + OFF_AHI + SWZ(aoff1 + ks * 32));
        ldsm4(l0, sb + OFF_ALO + SWZ(aoff0 + ks * 32));
        ldsm4(l1, sb + OFF_ALO + SWZ(aoff1 + ks * 32));
        #pragma unroll
        for (int p = 0; p < 4; p++) {
            const uint32_t bo = (chbase + p * 16 + bRowL) * 128 + bK16 + ks * 32;
            uint32_t bh[4], bl[4];
            ldsm4(bh, sb + OFF_BHI + SWZ(bo));
            ldsm4(bl, sb + OFF_BLO + SWZ(bo));
            float* A0 = acc + (p * 2) * 4;
            float* A1 = acc + (p * 2 + 1) * 4;
            float* B0 = acc + 32 + (p * 2) * 4;
            float* B1 = acc + 32 + (p * 2 + 1) * 4;
            mma16816(A0, a0, bh[0], bh[1]); mma16816(A1, a0, bh[2], bh[3]);
            mma16816(A0, a0, bl[0], bl[1]); mma16816(A1, a0, bl[2], bl[3]);
            mma16816(A0, l0, bh[0], bh[1]); mma16816(A1, l0, bh[2], bh[3]);
            mma16816(B0, a1, bh[0], bh[1]); mma16816(B1, a1, bh[2], bh[3]);
            mma16816(B0, a1, bl[0], bl[1]); mma16816(B1, a1, bl[2], bl[3]);
            mma16816(B0, l1, bh[0], bh[1]); mma16816(B1, l1, bh[2], bh[3]);
        }
    }
}

// ============================================================================
// Main kernel: one CTA per 128-row tile, 512 threads
// 16 warps = 4 m32-tiles x 4 col-groups (group g owns chunks 2g, 2g+1)
// ============================================================================
__global__ void __launch_bounds__(512, 1)
soft_kmeans_kernel(const float* __restrict__ z, const float* __restrict__ cc,
                   float* __restrict__ q_out, float* __restrict__ loss_out) {
    extern __shared__ char smem[];
    const uint32_t sb = smem_u32(smem);
    const int tid  = threadIdx.x;
    const int lane = tid & 31;
    const int wid  = tid >> 5;
    const int tile = blockIdx.x;
    const int mt   = wid & 3;     // rows mt*32 .. mt*32+31
    const int grp  = wid >> 2;    // cols grp*128 .. grp*128+127

    float* zsq_s = reinterpret_cast<float*>(smem + OFF_ZSQ);
    float* csq_s = reinterpret_cast<float*>(smem + OFF_CSQ);
    float* w_s   = reinterpret_cast<float*>(smem + OFF_W);
    float* mst_s = reinterpret_cast<float*>(smem + OFF_MST);
    float* red_s = reinterpret_cast<float*>(smem + OFF_RED);
    unsigned int* flag_s = reinterpret_cast<unsigned int*>(smem + OFF_RED + 64);

    // ---- Phase 0a: z tile; split hi/lo pre-scaled by 2*log2e ---------------
    {
        const float SC = 2.0f * LOG2E;
        const float4* zt = reinterpret_cast<const float4*>(z) + (size_t)tile * (TM * 64 / 4);
        #pragma unroll
        for (int it = 0; it < 4; it++) {
            const int idx = it * 512 + tid;
            const int row = idx >> 4, c4 = idx & 15;
            const float4 v = zt[idx];
            float sq = v.x * v.x + v.y * v.y + v.z * v.z + v.w * v.w;
            sq += __shfl_xor_sync(~0u, sq, 1);
            sq += __shfl_xor_sync(~0u, sq, 2);
            sq += __shfl_xor_sync(~0u, sq, 4);
            sq += __shfl_xor_sync(~0u, sq, 8);
            if ((lane & 15) == 0) zsq_s[row] = sq * LOG2E;   // zq' (log2 domain)
            uint2 hi, lo;
            split2(SC * v.x, SC * v.y, hi.x, lo.x);
            split2(SC * v.z, SC * v.w, hi.y, lo.y);
            const uint32_t so = SWZ((uint32_t)(row * 128 + c4 * 8));
            *reinterpret_cast<uint2*>(smem + OFF_AHI + so) = hi;
            *reinterpret_cast<uint2*>(smem + OFF_ALO + so) = lo;
        }
    }
    // ---- Phase 0b: all 512 centers; csq stored NEGATED + log2e-scaled ------
    {
        const float4* ct = reinterpret_cast<const float4*>(cc);
        #pragma unroll 4
        for (int it = 0; it < 16; it++) {
            const int idx = it * 512 + tid;
            const int row = idx >> 4, c4 = idx & 15;
            const float4 v = ct[idx];
            float sq = v.x * v.x + v.y * v.y + v.z * v.z + v.w * v.w;
            sq += __shfl_xor_sync(~0u, sq, 1);
            sq += __shfl_xor_sync(~0u, sq, 2);
            sq += __shfl_xor_sync(~0u, sq, 4);
            sq += __shfl_xor_sync(~0u, sq, 8);
            if ((lane & 15) == 0) csq_s[row] = -sq * LOG2E;  // ready-to-add addend
            uint2 hi, lo;
            split2(v.x, v.y, hi.x, lo.x);
            split2(v.z, v.w, hi.y, lo.y);
            const uint32_t so = SWZ((uint32_t)(row * 128 + c4 * 8));
            *reinterpret_cast<uint2*>(smem + OFF_BHI + so) = hi;
            *reinterpret_cast<uint2*>(smem + OFF_BLO + so) = lo;
        }
    }
    __syncthreads();

    // ---- lane decodes ------------------------------------------------------
    const int l8 = lane & 7;
    const uint32_t aCol16 = ((lane >> 4) & 1) * 16;
    const uint32_t aRow0  = (uint32_t)(mt * 32 + ((lane >> 3) & 1) * 8 + l8);
    const uint32_t aoff0  = aRow0 * 128 + aCol16;
    const uint32_t aoff1  = (aRow0 + 16) * 128 + aCol16;
    const uint32_t bRowL  = ((lane >> 4) & 1) * 8 + l8;
    const uint32_t bK16   = ((lane >> 3) & 1) * 16;

    const int rq = lane >> 2;
    int row_j[4];
    row_j[0] = mt * 32 + rq;   row_j[1] = row_j[0] + 8;
    row_j[2] = row_j[0] + 16;  row_j[3] = row_j[0] + 24;

    // e-staging bases (all 4 rows of a warp live in the same B half)
    uint32_t ebase[4];
    #pragma unroll
    for (int j = 0; j < 4; j++) {
        const int r = row_j[j];
        ebase[j] = (r < 64 ? OFF_BHI + (uint32_t)r * 128
                           : OFF_BLO + (uint32_t)(r - 64) * 128) + (lane & 3) * 4;
    }

    // online state over u = cross' - csq'  (zq cancels in softmax; folded back
    // into the loss at merge time)
    float m[4], s[4], tl[4];
    #pragma unroll
    for (int j = 0; j < 4; j++) { m[j] = -1e30f; s[j] = 0.f; tl[j] = 0.f; }

    // ---- Pass 1: group g processes its 2 chunks, decoupled from others -----
    #pragma unroll
    for (int ci = 0; ci < 2; ci++) {
        const int ch = grp * 2 + ci;
        const uint32_t chbase = (uint32_t)ch * 64;

        float acc[64];
        compute_chunk(acc, sb, chbase, aoff0, aoff1, bRowL, bK16);

        // u = cross' + (-csq'); chunk max per row-quad (same addend all rows)
        float cm[4] = {-1e30f, -1e30f, -1e30f, -1e30f};
        #pragma unroll
        for (int nt = 0; nt < 8; nt++) {
            const float2 cs = *reinterpret_cast<const float2*>(
                csq_s + chbase + nt * 8 + (lane & 3) * 2);
            float* A = acc + nt * 4;
            float* B = acc + 32 + nt * 4;
            A[0] += cs.x;  A[1] += cs.y;
            A[2] += cs.x;  A[3] += cs.y;
            B[0] += cs.x;  B[1] += cs.y;
            B[2] += cs.x;  B[3] += cs.y;
            cm[0] = fmaxf(cm[0], fmaxf(A[0], A[1]));
            cm[1] = fmaxf(cm[1], fmaxf(A[2], A[3]));
            cm[2] = fmaxf(cm[2], fmaxf(B[0], B[1]));
            cm[3] = fmaxf(cm[3], fmaxf(B[2], B[3]));
        }
        #pragma unroll
        for (int j = 0; j < 4; j++) {
            cm[j] = fmaxf(cm[j], __shfl_xor_sync(~0u, cm[j], 1));
            cm[j] = fmaxf(cm[j], __shfl_xor_sync(~0u, cm[j], 2));
            const float nm = fmaxf(m[j], cm[j]);
            const float f = ex2f(m[j] - nm);
            s[j] *= f; tl[j] *= f; m[j] = nm;
        }

        // exps (bare EX2) + running sums into regs BEFORE the group barrier
        uint32_t hp[4][8];
        #pragma unroll
        for (int nt = 0; nt < 8; nt++) {
            float* A = acc + nt * 4;
            float* B = acc + 32 + nt * 4;
            const float e00 = ex2f(A[0] - m[0]), e01 = ex2f(A[1] - m[0]);
            const float e10 = ex2f(A[2] - m[1]), e11 = ex2f(A[3] - m[1]);
            const float e20 = ex2f(B[0] - m[2]), e21 = ex2f(B[1] - m[2]);
            const float e30 = ex2f(B[2] - m[3]), e31 = ex2f(B[3] - m[3]);
            s[0] += e00 + e01;  tl[0] += e00 * A[0] + e01 * A[1];   // t_u = sum e*u
            s[1] += e10 + e11;  tl[1] += e10 * A[2] + e11 * A[3];
            s[2] += e20 + e21;  tl[2] += e20 * B[0] + e21 * B[1];
            s[3] += e30 + e31;  tl[3] += e30 * B[2] + e31 * B[3];
            const __half2 h0 = __floats2half2_rn(e00, e01);
            const __half2 h1 = __floats2half2_rn(e10, e11);
            const __half2 h2 = __floats2half2_rn(e20, e21);
            const __half2 h3 = __floats2half2_rn(e30, e31);
            hp[0][nt] = *reinterpret_cast<const uint32_t*>(&h0);
            hp[1][nt] = *reinterpret_cast<const uint32_t*>(&h1);
            hp[2][nt] = *reinterpret_cast<const uint32_t*>(&h2);
            hp[3][nt] = *reinterpret_cast<const uint32_t*>(&h3);
        }

        // group-local barrier: the 4 warps of group g are the ONLY readers of
        // B[ch]; once they arrive, aliasing B[ch] with e is safe.
        asm volatile("bar.sync %0, %1;" :: "r"(grp + 1), "r"(128) : "memory");

        const uint32_t chOff = (uint32_t)ch * 8192;
        #pragma unroll
        for (int j = 0; j < 4; j++) {
            const uint32_t eb = ebase[j] + chOff;
            #pragma unroll
            for (int nt = 0; nt < 8; nt++) {
                *reinterpret_cast<uint32_t*>(smem + eb + (uint32_t)((nt ^ rq) * 16)) = hp[j][nt];
            }
        }
        if ((lane & 3) == 0) {
            #pragma unroll
            for (int j = 0; j < 4; j++) w_s[row_j[j] * 9 + ch] = m[j];
        }
    }

    // ---- group-local row reductions + publish (m, s, t_u) ------------------
    #pragma unroll
    for (int j = 0; j < 4; j++) {
        s[j]  += __shfl_xor_sync(~0u, s[j], 1);
        s[j]  += __shfl_xor_sync(~0u, s[j], 2);
        tl[j] += __shfl_xor_sync(~0u, tl[j], 1);
        tl[j] += __shfl_xor_sync(~0u, tl[j], 2);
    }
    if ((lane & 3) == 0) {
        #pragma unroll
        for (int j = 0; j < 4; j++) {
            float* p = mst_s + (size_t)(grp * 128 + row_j[j]) * 4;
            p[0] = m[j]; p[1] = s[j]; p[2] = tl[j];
        }
    }
    __syncthreads();

    // ---- merge 4 groups per row (thread = row), weights, per-row loss ------
    // loss_row = (zq' - T_u/S) * ln2
    float lossr = 0.f;
    if (tid < TM) {
        float Mv = -1e30f;
        float mg[4], sg[4], tg[4];
        #pragma unroll
        for (int g = 0; g < 4; g++) {
            const float* p = mst_s + (size_t)(g * 128 + tid) * 4;
            mg[g] = p[0]; sg[g] = p[1]; tg[g] = p[2];
            Mv = fmaxf(Mv, mg[g]);
        }
        float sF = 0.f, tF = 0.f;
        #pragma unroll
        for (int g = 0; g < 4; g++) {
            const float f = ex2f(mg[g] - Mv);
            sF += sg[g] * f; tF += tg[g] * f;
        }
        const float inv = 1.f / sF;
        lossr = (zsq_s[tid] - tF * inv) * LN2;
        #pragma unroll
        for (int c = 0; c < 8; c++)
            w_s[tid * 9 + c] = ex2f(w_s[tid * 9 + c] - Mv) * inv;
    }
    #pragma unroll
    for (int o = 16; o; o >>= 1) lossr += __shfl_xor_sync(~0u, lossr, o);
    if (wid < 4 && lane == 0) red_s[wid] = lossr;
    __syncthreads();   // w_s + red_s ready
    if (tid == 0)
        g_loss_partial[tile] = red_s[0] + red_s[1] + red_s[2] + red_s[3];

    // ---- Pass 2: coalesced q write (16 warps x 32 rows x 128 cols) ---------
    {
        const int rbase = (wid >> 2) * 32;
        const int cb = (wid & 3) * 128 + lane * 4;
        const int ch = cb >> 6;
        const uint32_t chOff = (uint32_t)ch * 8192;
        const uint32_t inrow = (uint32_t)(lane & 15) * 8;
        float* qb = q_out + (size_t)tile * TM * KC + cb;
        #pragma unroll 4
        for (int r = 0; r < 32; r++) {
            const int row = rbase + r;
            const uint32_t base = (row < 64 ? OFF_BHI + (uint32_t)row * 128
                                            : OFF_BLO + (uint32_t)(row - 64) * 128) + chOff;
            const uint2 u = *reinterpret_cast<const uint2*>(
                smem + base + (inrow ^ (uint32_t)((row & 7) * 16)));
            const float2 f01 = __half22float2(*reinterpret_cast<const __half2*>(&u.x));
            const float2 f23 = __half22float2(*reinterpret_cast<const __half2*>(&u.y));
            const float w = w_s[row * 9 + ch];
            float4 o;
            o.x = f01.x * w; o.y = f01.y * w; o.z = f23.x * w; o.w = f23.y * w;
            *reinterpret_cast<float4*>(qb + (size_t)row * KC) = o;
        }
    }

    // ---- last-CTA loss finalize (deterministic fixed-order sum) ------------
    __threadfence();
    if (tid == 0) {
        const unsigned int old = atomicAdd(&g_done, 1u);
        *flag_s = (old == (unsigned int)(NTILES - 1)) ? 1u : 0u;
    }
    __syncthreads();
    if (*flag_s) {
        double a = 0.0;
        for (int i = tid; i < NTILES; i += 512) a += (double)g_loss_partial[i];
        #pragma unroll
        for (int o = 16; o; o >>= 1) a += __shfl_xor_sync(~0u, a, o);
        double* dred = reinterpret_cast<double*>(smem + OFF_RED + 128);
        if (lane == 0) dred[wid] = a;
        __syncthreads();
        if (tid == 0) {
            double t = 0.0;
            #pragma unroll
            for (int i = 0; i < 16; i++) t += dred[i];
            if (loss_out) *loss_out = (float)(t / (double)B_ROWS);
            g_done = 0;   // reset for next graph replay
        }
    }
}

// ============================================================================
// Launch
// ============================================================================
extern "C" void kernel_launch(void* const* d_in, const int* in_sizes, int n_in,
                              void* d_out, int out_size) {
    const float* z  = (const float*)d_in[0];
    const float* cc = (const float*)d_in[1];
    float* q = (float*)d_out;

    const long long q_elems = (long long)B_ROWS * KC;  // 67108864
    float* loss_out = ((long long)out_size > q_elems) ? (q + q_elems) : nullptr;

    cudaFuncSetAttribute(soft_kmeans_kernel,
                         cudaFuncAttributeMaxDynamicSharedMemorySize, SMEM_BYTES);
    soft_kmeans_kernel<<<NTILES, 512, SMEM_BYTES>>>(z, cc, q, loss_out);
}